// round 3
// baseline (speedup 1.0000x reference)
#include <cuda_runtime.h>
#include <math.h>
#include <stddef.h>

#define BB 2
#define TT 1024
#define CC 1024
#define NHH 16
#define DHH 64
#define LL 4
#define HF 2816
#define FT 9
#define MM (BB*TT)
#define C3 (3*CC)      // fused qkv row stride
#define HF2 (2*HF)     // fused w1|w2 row stride

// ---------------- scratch (static device globals; no allocation) ----------------
__device__ float g_h  [MM*CC];
__device__ float g_nrm[MM*CC];
__device__ float g_qkv[MM*C3];
__device__ float g_att[MM*CC];
__device__ float g_f12[(size_t)MM*HF2];
__device__ float g_f1 [(size_t)MM*HF];

// ---------------- input projection: h[m,c] = sum_f x[m,f] * w_in[c,f] ----------------
__global__ void k_inproj(const float* __restrict__ x, const float* __restrict__ w_in,
                         float* __restrict__ h)
{
    int m = blockIdx.x;
    __shared__ float xs[FT];
    if (threadIdx.x < FT) xs[threadIdx.x] = x[m*FT + threadIdx.x];
    __syncthreads();
    for (int c = threadIdx.x; c < CC; c += blockDim.x) {
        float acc = 0.f;
        #pragma unroll
        for (int f = 0; f < FT; f++) acc += xs[f] * w_in[c*FT + f];
        h[(size_t)m*CC + c] = acc;
    }
}

// ---------------- RMSNorm: out = in * rsqrt(mean(in^2)+eps) * g ----------------
__global__ void k_rms(const float* __restrict__ in, const float* __restrict__ g,
                      float* __restrict__ out)
{
    int m = blockIdx.x;
    const float* row = in + (size_t)m*CC;
    float ss = 0.f;
    for (int c = threadIdx.x; c < CC; c += 256) { float v = row[c]; ss += v*v; }
    __shared__ float red[8];
    #pragma unroll
    for (int o = 16; o; o >>= 1) ss += __shfl_xor_sync(0xffffffffu, ss, o);
    if ((threadIdx.x & 31) == 0) red[threadIdx.x >> 5] = ss;
    __syncthreads();
    if (threadIdx.x < 8) {
        float v = red[threadIdx.x];
        #pragma unroll
        for (int o = 4; o; o >>= 1) v += __shfl_xor_sync(0xffu, v, o);
        if (threadIdx.x == 0) red[0] = v;
    }
    __syncthreads();
    float r = rsqrtf(red[0] * (1.0f/CC) + 1e-5f);
    for (int c = threadIdx.x; c < CC; c += 256)
        out[(size_t)m*CC + c] = row[c] * r * g[c];
}

// ---------------- SGEMM: O[m, n0+j] = epilogue( sum_k A[m,k]*W[n,k] ) ----------------
// Weight selected per block column: n0 < nsplit -> W0 (row n0), else W1 (row n0-nsplit).
// MODE 0: O = acc ;  MODE 1: O = R + acc (R indexed with stride No)
// BM=BN=128, BK=16, 256 threads, 8x8/thread, double-buffered smem (1 barrier/tile),
// register prefetch of global tiles.
template<int MODE>
__global__ void __launch_bounds__(256) k_gemm(const float* __restrict__ A,
                                              const float* __restrict__ W0,
                                              const float* W1, int nsplit,
                                              const float* R, float* O,
                                              int No, int K)
{
    __shared__ float As[2][16][128];
    __shared__ float Bs[2][16][128];
    const int tid = threadIdx.x;
    const int tx = tid & 15, ty = tid >> 4;
    const int m0 = blockIdx.y << 7, n0 = blockIdx.x << 7;
    const int lr = tid >> 1;          // 0..127
    const int lk = (tid & 1) << 3;    // 0 or 8

    const float* Wbase = (W1 != nullptr && n0 >= nsplit)
                       ? (W1 + (size_t)(n0 - nsplit) * K)
                       : (W0 + (size_t)n0 * K);
    const float* Ap = A + (size_t)(m0 + lr) * K + lk;
    const float* Wp = Wbase + (size_t)lr * K + lk;

    float4 pa0 = *(const float4*)Ap;
    float4 pa1 = *(const float4*)(Ap + 4);
    float4 pb0 = *(const float4*)Wp;
    float4 pb1 = *(const float4*)(Wp + 4);

    float acc[8][8];
    #pragma unroll
    for (int i = 0; i < 8; i++)
        #pragma unroll
        for (int j = 0; j < 8; j++) acc[i][j] = 0.f;

    // store tile 0 into buffer 0
    As[0][lk+0][lr]=pa0.x; As[0][lk+1][lr]=pa0.y; As[0][lk+2][lr]=pa0.z; As[0][lk+3][lr]=pa0.w;
    As[0][lk+4][lr]=pa1.x; As[0][lk+5][lr]=pa1.y; As[0][lk+6][lr]=pa1.z; As[0][lk+7][lr]=pa1.w;
    Bs[0][lk+0][lr]=pb0.x; Bs[0][lk+1][lr]=pb0.y; Bs[0][lk+2][lr]=pb0.z; Bs[0][lk+3][lr]=pb0.w;
    Bs[0][lk+4][lr]=pb1.x; Bs[0][lk+5][lr]=pb1.y; Bs[0][lk+6][lr]=pb1.z; Bs[0][lk+7][lr]=pb1.w;
    __syncthreads();

    const int nt = K >> 4;
    int p = 0;
    for (int kt = 0; kt < nt; kt++) {
        if (kt + 1 < nt) {
            Ap += 16; Wp += 16;
            pa0 = *(const float4*)Ap;
            pa1 = *(const float4*)(Ap + 4);
            pb0 = *(const float4*)Wp;
            pb1 = *(const float4*)(Wp + 4);
        }
        #pragma unroll
        for (int kk = 0; kk < 16; kk++) {
            float4 a0 = *(const float4*)&As[p][kk][ty<<2];
            float4 a1 = *(const float4*)&As[p][kk][64 + (ty<<2)];
            float4 b0 = *(const float4*)&Bs[p][kk][tx<<2];
            float4 b1 = *(const float4*)&Bs[p][kk][64 + (tx<<2)];
            float av[8] = {a0.x,a0.y,a0.z,a0.w, a1.x,a1.y,a1.z,a1.w};
            float bv[8] = {b0.x,b0.y,b0.z,b0.w, b1.x,b1.y,b1.z,b1.w};
            #pragma unroll
            for (int i = 0; i < 8; i++)
                #pragma unroll
                for (int j = 0; j < 8; j++)
                    acc[i][j] += av[i] * bv[j];
        }
        if (kt + 1 < nt) {
            int q = p ^ 1;
            As[q][lk+0][lr]=pa0.x; As[q][lk+1][lr]=pa0.y; As[q][lk+2][lr]=pa0.z; As[q][lk+3][lr]=pa0.w;
            As[q][lk+4][lr]=pa1.x; As[q][lk+5][lr]=pa1.y; As[q][lk+6][lr]=pa1.z; As[q][lk+7][lr]=pa1.w;
            Bs[q][lk+0][lr]=pb0.x; Bs[q][lk+1][lr]=pb0.y; Bs[q][lk+2][lr]=pb0.z; Bs[q][lk+3][lr]=pb0.w;
            Bs[q][lk+4][lr]=pb1.x; Bs[q][lk+5][lr]=pb1.y; Bs[q][lk+6][lr]=pb1.z; Bs[q][lk+7][lr]=pb1.w;
            __syncthreads();
            p = q;
        }
    }

    // epilogue
    #pragma unroll
    for (int i = 0; i < 8; i++) {
        int r = m0 + ((i < 4) ? ((ty<<2) + i) : (64 + (ty<<2) + i - 4));
        float* op = O + (size_t)r * No + n0;
        float4 o0 = make_float4(acc[i][0], acc[i][1], acc[i][2], acc[i][3]);
        float4 o1 = make_float4(acc[i][4], acc[i][5], acc[i][6], acc[i][7]);
        if (MODE == 1) {
            const float* rp = R + (size_t)r * No + n0;
            float4 r0 = *(const float4*)(rp + (tx<<2));
            float4 r1 = *(const float4*)(rp + 64 + (tx<<2));
            o0.x += r0.x; o0.y += r0.y; o0.z += r0.z; o0.w += r0.w;
            o1.x += r1.x; o1.y += r1.y; o1.z += r1.z; o1.w += r1.w;
        }
        *(float4*)(op + (tx<<2)) = o0;
        *(float4*)(op + 64 + (tx<<2)) = o1;
    }
}

// ---------------- RoPE in-place on q and k parts of fused qkv [M, 3C] ----------------
__global__ void k_rope(float* __restrict__ qkv)
{
    int idx = blockIdx.x * blockDim.x + threadIdx.x;   // MM*NHH*32 threads
    if (idx >= MM*NHH*32) return;
    int i  = idx & 31;
    int hh = (idx >> 5) & (NHH - 1);
    int m  = idx >> 9;
    int t  = m & (TT - 1);
    // inv_freq = 10000^(-i/32) = exp(-i * ln(10000)/32)
    float freq = __expf(-(float)i * 0.2878231366f);
    float ang = (float)t * freq;
    float s, c;
    __sincosf(ang, &s, &c);
    size_t qb = (size_t)m*C3 + hh*DHH + i;
    float q1 = qkv[qb], q2 = qkv[qb + 32];
    qkv[qb]      = q1*c - q2*s;
    qkv[qb + 32] = q2*c + q1*s;
    size_t kb = qb + CC;
    float k1 = qkv[kb], k2 = qkv[kb + 32];
    qkv[kb]      = k1*c - k2*s;
    qkv[kb + 32] = k2*c + k1*s;
}

// ---------------- Flash attention (fp32, 64x64 tiles, online softmax) ----------------
// grid: (TT/64, BB*NHH), block 256. Reads fused qkv [M, 3C].
#define ATTN_SMEM (4*64*68*4)

__global__ void __launch_bounds__(256) k_attn(const float* __restrict__ qkv,
                                              float* __restrict__ out)
{
    extern __shared__ float sm[];
    float (*Qs)[68] = (float(*)[68])(sm);
    float (*Ks)[68] = (float(*)[68])(sm + 64*68);
    float (*Vs)[68] = (float(*)[68])(sm + 2*64*68);
    float (*Ps)[68] = (float(*)[68])(sm + 3*64*68);

    const int bh = blockIdx.y;
    const int b = bh / NHH, hh = bh % NHH;
    const int qt = gridDim.x - 1 - blockIdx.x;   // long blocks launch first
    const int t0 = qt * 64;
    const int tid = threadIdx.x;
    const int tx = tid & 15, ty = tid >> 4;
    const float scale = 0.125f;  // 1/sqrt(64)

    // load Q tile (transposed, pre-scaled)
    {
        int r = tid >> 2, d0 = (tid & 3) * 16;
        const float* src = qkv + ((size_t)(b*TT + t0 + r))*C3 + hh*DHH + d0;
        #pragma unroll
        for (int v = 0; v < 4; v++) {
            float4 f = *(const float4*)(src + v*4);
            Qs[d0+v*4+0][r] = f.x*scale; Qs[d0+v*4+1][r] = f.y*scale;
            Qs[d0+v*4+2][r] = f.z*scale; Qs[d0+v*4+3][r] = f.w*scale;
        }
    }

    float accO[4][4];
    float mrow[4], lrow[4];
    #pragma unroll
    for (int i = 0; i < 4; i++) {
        mrow[i] = -1e30f; lrow[i] = 0.f;
        #pragma unroll
        for (int j = 0; j < 4; j++) accO[i][j] = 0.f;
    }

    const int nst = qt + 1;
    for (int st = 0; st < nst; st++) {
        int s0 = st * 64;
        // load K (transposed) and V (natural) tiles
        {
            int r = tid >> 2, d0 = (tid & 3) * 16;
            const float* kp = qkv + ((size_t)(b*TT + s0 + r))*C3 + CC + hh*DHH + d0;
            const float* vp = kp + CC;
            #pragma unroll
            for (int v = 0; v < 4; v++) {
                float4 f = *(const float4*)(kp + v*4);
                Ks[d0+v*4+0][r] = f.x; Ks[d0+v*4+1][r] = f.y;
                Ks[d0+v*4+2][r] = f.z; Ks[d0+v*4+3][r] = f.w;
                *(float4*)&Vs[r][d0+v*4] = *(const float4*)(vp + v*4);
            }
        }
        __syncthreads();

        // S = (Q*scale) K^T ; thread tile: rows 4ty+i, cols 4tx+j
        float s[4][4] = {{0,0,0,0},{0,0,0,0},{0,0,0,0},{0,0,0,0}};
        #pragma unroll
        for (int d = 0; d < DHH; d++) {
            float4 qa = *(const float4*)&Qs[d][ty<<2];
            float4 kb = *(const float4*)&Ks[d][tx<<2];
            s[0][0]+=qa.x*kb.x; s[0][1]+=qa.x*kb.y; s[0][2]+=qa.x*kb.z; s[0][3]+=qa.x*kb.w;
            s[1][0]+=qa.y*kb.x; s[1][1]+=qa.y*kb.y; s[1][2]+=qa.y*kb.z; s[1][3]+=qa.y*kb.w;
            s[2][0]+=qa.z*kb.x; s[2][1]+=qa.z*kb.y; s[2][2]+=qa.z*kb.z; s[2][3]+=qa.z*kb.w;
            s[3][0]+=qa.w*kb.x; s[3][1]+=qa.w*kb.y; s[3][2]+=qa.w*kb.z; s[3][3]+=qa.w*kb.w;
        }
        // causal mask on diagonal tile
        if (st == nst - 1) {
            #pragma unroll
            for (int i = 0; i < 4; i++)
                #pragma unroll
                for (int j = 0; j < 4; j++)
                    if ((tx<<2)+j > (ty<<2)+i) s[i][j] = -1e30f;
        }
        // online softmax update
        #pragma unroll
        for (int i = 0; i < 4; i++) {
            float rmax = fmaxf(fmaxf(s[i][0], s[i][1]), fmaxf(s[i][2], s[i][3]));
            #pragma unroll
            for (int o = 1; o < 16; o <<= 1)
                rmax = fmaxf(rmax, __shfl_xor_sync(0xffffffffu, rmax, o));
            float mn = fmaxf(mrow[i], rmax);
            float corr = __expf(mrow[i] - mn);
            float rs = 0.f;
            #pragma unroll
            for (int j = 0; j < 4; j++) { s[i][j] = __expf(s[i][j] - mn); rs += s[i][j]; }
            #pragma unroll
            for (int o = 1; o < 16; o <<= 1)
                rs += __shfl_xor_sync(0xffffffffu, rs, o);
            lrow[i] = lrow[i]*corr + rs;
            mrow[i] = mn;
            #pragma unroll
            for (int j = 0; j < 4; j++) accO[i][j] *= corr;
            *(float4*)&Ps[(ty<<2)+i][tx<<2] = make_float4(s[i][0], s[i][1], s[i][2], s[i][3]);
        }
        __syncthreads();

        // accO += P @ V ; dims of this thread: 4tx+j
        #pragma unroll
        for (int ss = 0; ss < 64; ss++) {
            float4 vv = *(const float4*)&Vs[ss][tx<<2];
            #pragma unroll
            for (int i = 0; i < 4; i++) {
                float p = Ps[(ty<<2)+i][ss];
                accO[i][0] += p*vv.x; accO[i][1] += p*vv.y;
                accO[i][2] += p*vv.z; accO[i][3] += p*vv.w;
            }
        }
        __syncthreads();
    }

    // write O (normalized)
    #pragma unroll
    for (int i = 0; i < 4; i++) {
        float inv = 1.f / lrow[i];
        float* op = out + ((size_t)(b*TT + t0 + (ty<<2) + i))*CC + hh*DHH + (tx<<2);
        *(float4*)op = make_float4(accO[i][0]*inv, accO[i][1]*inv, accO[i][2]*inv, accO[i][3]*inv);
    }
}

// ---------------- SiLU gate on fused f12 [M, 2*HF]: f1 = silu(f12[:, :HF]) * f12[:, HF:] ----------------
__global__ void k_silu(const float* __restrict__ f12, float* __restrict__ f1)
{
    int i = blockIdx.x * 256 + threadIdx.x;   // MM*HF threads
    if (i >= MM*HF) return;
    int m = i / HF, j = i - m*HF;
    float a = f12[(size_t)m*HF2 + j];
    float b = f12[(size_t)m*HF2 + HF + j];
    f1[i] = a / (1.f + __expf(-a)) * b;
}

// ---------------- launcher ----------------
extern "C" void kernel_launch(void* const* d_in, const int* in_sizes, int n_in,
                              void* d_out, int out_size)
{
    const float* x    = (const float*)d_in[0];
    const float* w_in = (const float*)d_in[1];
    const float* wq   = (const float*)d_in[2];
    const float* wkv  = (const float*)d_in[3];
    const float* wo   = (const float*)d_in[4];
    const float* w1   = (const float*)d_in[5];
    const float* w2   = (const float*)d_in[6];
    const float* w3   = (const float*)d_in[7];
    const float* g1   = (const float*)d_in[8];
    const float* g2   = (const float*)d_in[9];
    const float* gf   = (const float*)d_in[10];
    float* out = (float*)d_out;

    float *h, *nrm, *qkv, *att, *f12, *f1;
    cudaGetSymbolAddress((void**)&h,   g_h);
    cudaGetSymbolAddress((void**)&nrm, g_nrm);
    cudaGetSymbolAddress((void**)&qkv, g_qkv);
    cudaGetSymbolAddress((void**)&att, g_att);
    cudaGetSymbolAddress((void**)&f12, g_f12);
    cudaGetSymbolAddress((void**)&f1,  g_f1);

    cudaFuncSetAttribute((const void*)k_attn,
                         cudaFuncAttributeMaxDynamicSharedMemorySize, ATTN_SMEM);

    k_inproj<<<MM, 256>>>(x, w_in, h);

    for (int l = 0; l < LL; l++) {
        const float* wq_l  = wq  + (size_t)l*CC*CC;
        const float* wkv_l = wkv + (size_t)l*2*CC*CC;
        const float* wo_l  = wo  + (size_t)l*CC*CC;
        const float* w1_l  = w1  + (size_t)l*HF*CC;
        const float* w2_l  = w2  + (size_t)l*HF*CC;
        const float* w3_l  = w3  + (size_t)l*CC*HF;

        // attention block
        k_rms<<<MM, 256>>>(h, g1 + l*CC, nrm);
        // fused q|kv projection: N = 3C, wq for n<1024, wkv after
        k_gemm<0><<<dim3(C3/128, MM/128), 256>>>(nrm, wq_l, wkv_l, CC, nullptr, qkv, C3, CC);
        k_rope<<<(MM*NHH*32)/256, 256>>>(qkv);
        k_attn<<<dim3(TT/64, BB*NHH), 256, ATTN_SMEM>>>(qkv, att);
        k_gemm<1><<<dim3(CC/128, MM/128), 256>>>(att, wo_l, nullptr, 0, h, h, CC, CC);

        // MLP block
        k_rms<<<MM, 256>>>(h, g2 + l*CC, nrm);
        // fused w1|w2: N = 2*HF, w1 for n<HF, w2 after
        k_gemm<0><<<dim3(HF2/128, MM/128), 256>>>(nrm, w1_l, w2_l, HF, nullptr, f12, HF2, CC);
        k_silu<<<(MM*HF + 255)/256, 256>>>(f12, f1);
        k_gemm<1><<<dim3(CC/128, MM/128), 256>>>(f1, w3_l, nullptr, 0, h, h, CC, HF);
    }

    k_rms<<<MM, 256>>>(h, gf, out);
}

// round 5
// speedup vs baseline: 2.1535x; 2.1535x over previous
#include <cuda_runtime.h>
#include <cuda_bf16.h>
#include <math.h>
#include <stddef.h>
#include <stdint.h>

#define BB 2
#define TT 1024
#define CC 1024
#define NHH 16
#define DHH 64
#define LL 4
#define HF 2816
#define FT 9
#define MM (BB*TT)
#define C3 (3*CC)
#define HF2 (2*HF)

// ---------------- scratch (static device globals; no allocation) ----------------
__device__ __align__(256) float g_h  [MM*CC];
__device__ __align__(256) float g_qkv[MM*C3];
__device__ __align__(256) float g_f12[(size_t)MM*HF2];

// bf16 hi/lo activation buffers (sized for largest A: [MM, HF])
__device__ __align__(256) __nv_bfloat16 g_ah[(size_t)MM*HF];
__device__ __align__(256) __nv_bfloat16 g_al[(size_t)MM*HF];

// bf16 hi/lo weights (all layers)
__device__ __align__(256) __nv_bfloat16 g_wq_h [(size_t)LL*CC*CC];
__device__ __align__(256) __nv_bfloat16 g_wq_l [(size_t)LL*CC*CC];
__device__ __align__(256) __nv_bfloat16 g_wkv_h[(size_t)LL*2*CC*CC];
__device__ __align__(256) __nv_bfloat16 g_wkv_l[(size_t)LL*2*CC*CC];
__device__ __align__(256) __nv_bfloat16 g_wo_h [(size_t)LL*CC*CC];
__device__ __align__(256) __nv_bfloat16 g_wo_l [(size_t)LL*CC*CC];
__device__ __align__(256) __nv_bfloat16 g_w1_h [(size_t)LL*HF*CC];
__device__ __align__(256) __nv_bfloat16 g_w1_l [(size_t)LL*HF*CC];
__device__ __align__(256) __nv_bfloat16 g_w2_h [(size_t)LL*HF*CC];
__device__ __align__(256) __nv_bfloat16 g_w2_l [(size_t)LL*HF*CC];
__device__ __align__(256) __nv_bfloat16 g_w3_h [(size_t)LL*CC*HF];
__device__ __align__(256) __nv_bfloat16 g_w3_l [(size_t)LL*CC*HF];

// ---------------- helpers ----------------
__device__ __forceinline__ void split1(float v, __nv_bfloat16& h, __nv_bfloat16& l)
{
    h = __float2bfloat16(v);
    l = __float2bfloat16(v - __bfloat162float(h));
}

// split fp32 -> bf16 hi/lo, 4 elems/thread (n multiple of 4)
__global__ void k_split(const float* __restrict__ x, __nv_bfloat16* __restrict__ hi,
                        __nv_bfloat16* __restrict__ lo, int n)
{
    int i = (blockIdx.x*256 + threadIdx.x)*4;
    if (i >= n) return;
    float4 v = *(const float4*)(x + i);
    __nv_bfloat16 h4[4], l4[4];
    split1(v.x, h4[0], l4[0]); split1(v.y, h4[1], l4[1]);
    split1(v.z, h4[2], l4[2]); split1(v.w, h4[3], l4[3]);
    *(uint2*)(hi + i) = *(uint2*)h4;
    *(uint2*)(lo + i) = *(uint2*)l4;
}

// SiLU gate + split: g = silu(f12[:, :HF]) * f12[:, HF:] -> bf16 hi/lo [MM,HF]
__global__ void k_silu_split(const float* __restrict__ f12,
                             __nv_bfloat16* __restrict__ hi,
                             __nv_bfloat16* __restrict__ lo)
{
    int i = (blockIdx.x*256 + threadIdx.x)*4;   // over MM*HF
    if (i >= MM*HF) return;
    int m = i / HF, j = i - m*HF;
    float4 a = *(const float4*)&f12[(size_t)m*HF2 + j];
    float4 b = *(const float4*)&f12[(size_t)m*HF2 + HF + j];
    float v0 = a.x / (1.f + __expf(-a.x)) * b.x;
    float v1 = a.y / (1.f + __expf(-a.y)) * b.y;
    float v2 = a.z / (1.f + __expf(-a.z)) * b.z;
    float v3 = a.w / (1.f + __expf(-a.w)) * b.w;
    __nv_bfloat16 h4[4], l4[4];
    split1(v0, h4[0], l4[0]); split1(v1, h4[1], l4[1]);
    split1(v2, h4[2], l4[2]); split1(v3, h4[3], l4[3]);
    *(uint2*)(hi + i) = *(uint2*)h4;
    *(uint2*)(lo + i) = *(uint2*)l4;
}

// ---------------- input projection ----------------
__global__ void k_inproj(const float* __restrict__ x, const float* __restrict__ w_in,
                         float* __restrict__ h)
{
    int m = blockIdx.x;
    __shared__ float xs[FT];
    if (threadIdx.x < FT) xs[threadIdx.x] = x[m*FT + threadIdx.x];
    __syncthreads();
    for (int c = threadIdx.x; c < CC; c += blockDim.x) {
        float acc = 0.f;
        #pragma unroll
        for (int f = 0; f < FT; f++) acc += xs[f] * w_in[c*FT + f];
        h[(size_t)m*CC + c] = acc;
    }
}

// ---------------- RMSNorm -> fp32 out (final) ----------------
__global__ void k_rms(const float* __restrict__ in, const float* __restrict__ g,
                      float* __restrict__ out)
{
    int m = blockIdx.x;
    const float* row = in + (size_t)m*CC;
    float ss = 0.f;
    for (int c = threadIdx.x; c < CC; c += 256) { float v = row[c]; ss += v*v; }
    __shared__ float red[8];
    #pragma unroll
    for (int o = 16; o; o >>= 1) ss += __shfl_xor_sync(0xffffffffu, ss, o);
    if ((threadIdx.x & 31) == 0) red[threadIdx.x >> 5] = ss;
    __syncthreads();
    if (threadIdx.x < 8) {
        float v = red[threadIdx.x];
        #pragma unroll
        for (int o = 4; o; o >>= 1) v += __shfl_xor_sync(0xffu, v, o);
        if (threadIdx.x == 0) red[0] = v;
    }
    __syncthreads();
    float r = rsqrtf(red[0] * (1.0f/CC) + 1e-5f);
    for (int c = threadIdx.x; c < CC; c += 256)
        out[(size_t)m*CC + c] = row[c] * r * g[c];
}

// ---------------- RMSNorm -> bf16 hi/lo (fused, feeds GEMM directly) ----------------
__global__ void k_rms_split(const float* __restrict__ in, const float* __restrict__ g,
                            __nv_bfloat16* __restrict__ hi, __nv_bfloat16* __restrict__ lo)
{
    int m = blockIdx.x;
    const float* row = in + (size_t)m*CC;
    float ss = 0.f;
    float4 v[1];
    {
        // CC=1024, 256 threads -> one float4 per thread
        v[0] = *(const float4*)(row + threadIdx.x*4);
        ss = v[0].x*v[0].x + v[0].y*v[0].y + v[0].z*v[0].z + v[0].w*v[0].w;
    }
    __shared__ float red[8];
    #pragma unroll
    for (int o = 16; o; o >>= 1) ss += __shfl_xor_sync(0xffffffffu, ss, o);
    if ((threadIdx.x & 31) == 0) red[threadIdx.x >> 5] = ss;
    __syncthreads();
    if (threadIdx.x < 8) {
        float t = red[threadIdx.x];
        #pragma unroll
        for (int o = 4; o; o >>= 1) t += __shfl_xor_sync(0xffu, t, o);
        if (threadIdx.x == 0) red[0] = t;
    }
    __syncthreads();
    float r = rsqrtf(red[0] * (1.0f/CC) + 1e-5f);
    int c = threadIdx.x*4;
    const float4 gv = *(const float4*)(g + c);
    float o0 = v[0].x*r*gv.x, o1 = v[0].y*r*gv.y, o2 = v[0].z*r*gv.z, o3 = v[0].w*r*gv.w;
    __nv_bfloat16 h4[4], l4[4];
    split1(o0, h4[0], l4[0]); split1(o1, h4[1], l4[1]);
    split1(o2, h4[2], l4[2]); split1(o3, h4[3], l4[3]);
    *(uint2*)(hi + (size_t)m*CC + c) = *(uint2*)h4;
    *(uint2*)(lo + (size_t)m*CC + c) = *(uint2*)l4;
}

// ---------------- bf16-split tensor-core GEMM ----------------
// O[m,n] = epi( sum_k A[m,k]*W[n,k] ), A ~ Ah+Al, W ~ Wh+Wl (drop Al*Wl).
// CTA tile 128x128x32, 8 warps (4 m x 2 n), warp tile 32x64, mma.m16n8k16.
// 3-stage cp.async pipeline; smem rows padded to 40 bf16 (80B) -> conflict-free ldmatrix.
#define LDT 40
#define STG_B (128*LDT*2)        // bytes per array per stage (10240)
#define SS_B  (4*STG_B)          // bytes per stage (40960)
#define MMA_SMEM (3*SS_B)        // 122880

#define LDSM4(r, addr) \
    asm volatile("ldmatrix.sync.aligned.m8n8.x4.shared.b16 {%0,%1,%2,%3}, [%4];" \
        : "=r"((r)[0]), "=r"((r)[1]), "=r"((r)[2]), "=r"((r)[3]) : "r"(addr))
#define LDSM2(r0, r1, addr) \
    asm volatile("ldmatrix.sync.aligned.m8n8.x2.shared.b16 {%0,%1}, [%2];" \
        : "=r"(r0), "=r"(r1) : "r"(addr))
#define MMA16816(d, a, b0, b1) \
    asm volatile("mma.sync.aligned.m16n8k16.row.col.f32.bf16.bf16.f32 " \
        "{%0,%1,%2,%3}, {%4,%5,%6,%7}, {%8,%9}, {%0,%1,%2,%3};" \
        : "+f"((d)[0]), "+f"((d)[1]), "+f"((d)[2]), "+f"((d)[3]) \
        : "r"((a)[0]), "r"((a)[1]), "r"((a)[2]), "r"((a)[3]), "r"(b0), "r"(b1))

__device__ __forceinline__ void stage_load(uint32_t s_base, const __nv_bfloat16* g_base,
                                           int K, int k0)
{
    int tid = threadIdx.x;
    #pragma unroll
    for (int i = 0; i < 2; i++) {
        int c = tid + i*256;              // 0..511
        int row = c >> 2, col = c & 3;
        uint32_t dst = s_base + (uint32_t)(row*LDT + col*8)*2;
        const __nv_bfloat16* src = g_base + (size_t)row*K + k0 + col*8;
        asm volatile("cp.async.cg.shared.global [%0], [%1], 16;" :: "r"(dst), "l"(src));
    }
}

template<int MODE>   // 0: O=acc ; 1: O=R+acc
__global__ void __launch_bounds__(256) k_mma(
    const __nv_bfloat16* __restrict__ Ah, const __nv_bfloat16* __restrict__ Al,
    const __nv_bfloat16* __restrict__ W0h, const __nv_bfloat16* __restrict__ W0l,
    const __nv_bfloat16* W1h, const __nv_bfloat16* W1l, int nsplit,
    const float* R, float* O, int No, int K)
{
    extern __shared__ __nv_bfloat16 smem[];
    const int m0 = blockIdx.y << 7, n0 = blockIdx.x << 7;

    const __nv_bfloat16 *Wh, *Wl;
    if (W1h != nullptr && n0 >= nsplit) {
        Wh = W1h + (size_t)(n0 - nsplit)*K;
        Wl = W1l + (size_t)(n0 - nsplit)*K;
    } else {
        Wh = W0h + (size_t)n0*K;
        Wl = W0l + (size_t)n0*K;
    }
    const __nv_bfloat16* Am_h = Ah + (size_t)m0*K;
    const __nv_bfloat16* Am_l = Al + (size_t)m0*K;

    uint32_t s0 = (uint32_t)__cvta_generic_to_shared(smem);
    const int nt = K >> 5;

    // prefetch stages 0,1
    #pragma unroll
    for (int p = 0; p < 2; p++) {
        uint32_t sb = s0 + p*SS_B;
        stage_load(sb,           Am_h, K, p*32);
        stage_load(sb + STG_B,   Am_l, K, p*32);
        stage_load(sb + 2*STG_B, Wh,   K, p*32);
        stage_load(sb + 3*STG_B, Wl,   K, p*32);
        asm volatile("cp.async.commit_group;");
    }

    const int lane = threadIdx.x & 31, wid = threadIdx.x >> 5;
    const int wm = (wid & 3) << 5;    // 0,32,64,96
    const int wn = (wid >> 2) << 6;   // 0,64

    float acc[2][8][4];
    #pragma unroll
    for (int a = 0; a < 2; a++)
        #pragma unroll
        for (int b = 0; b < 8; b++)
            #pragma unroll
            for (int c = 0; c < 4; c++) acc[a][b][c] = 0.f;

    const int a_row_lane = (lane & 7) + ((lane >> 3) & 1)*8;
    const int a_kadd = (lane >> 4)*8;
    const int lane16 = lane & 15;
    const int b_row_lane = lane16 & 7;
    const int b_kadd = (lane16 >> 3)*8;

    for (int kt = 0; kt < nt; kt++) {
        asm volatile("cp.async.wait_group 1;");
        __syncthreads();
        uint32_t sb = s0 + (uint32_t)(kt % 3)*SS_B;

        #pragma unroll
        for (int ka = 0; ka < 2; ka++) {
            uint32_t ahr[2][4], alr[2][4];
            #pragma unroll
            for (int ma = 0; ma < 2; ma++) {
                uint32_t ad = sb + (uint32_t)(((wm + ma*16 + a_row_lane)*LDT
                                               + ka*16 + a_kadd) << 1);
                LDSM4(ahr[ma], ad);
                LDSM4(alr[ma], ad + STG_B);
            }
            #pragma unroll
            for (int nb = 0; nb < 8; nb++) {
                uint32_t bd = sb + 2*STG_B + (uint32_t)(((wn + nb*8 + b_row_lane)*LDT
                                                         + ka*16 + b_kadd) << 1);
                uint32_t bh0, bh1, bl0, bl1;
                LDSM2(bh0, bh1, bd);
                LDSM2(bl0, bl1, bd + STG_B);
                #pragma unroll
                for (int ma = 0; ma < 2; ma++) {
                    MMA16816(acc[ma][nb], ahr[ma], bh0, bh1);
                    MMA16816(acc[ma][nb], ahr[ma], bl0, bl1);
                    MMA16816(acc[ma][nb], alr[ma], bh0, bh1);
                }
            }
        }

        int kn = kt + 2;
        if (kn < nt) {
            uint32_t sb2 = s0 + (uint32_t)(kn % 3)*SS_B;
            stage_load(sb2,           Am_h, K, kn*32);
            stage_load(sb2 + STG_B,   Am_l, K, kn*32);
            stage_load(sb2 + 2*STG_B, Wh,   K, kn*32);
            stage_load(sb2 + 3*STG_B, Wl,   K, kn*32);
        }
        asm volatile("cp.async.commit_group;");
    }

    // epilogue
    const int quad = lane >> 2, tq = lane & 3;
    #pragma unroll
    for (int ma = 0; ma < 2; ma++) {
        #pragma unroll
        for (int nb = 0; nb < 8; nb++) {
            int r = m0 + wm + ma*16 + quad;
            int c = n0 + wn + nb*8 + tq*2;
            float2 v0 = make_float2(acc[ma][nb][0], acc[ma][nb][1]);
            float2 v1 = make_float2(acc[ma][nb][2], acc[ma][nb][3]);
            if (MODE == 1) {
                float2 r0 = *(const float2*)&R[(size_t)r*No + c];
                float2 r1 = *(const float2*)&R[(size_t)(r+8)*No + c];
                v0.x += r0.x; v0.y += r0.y;
                v1.x += r1.x; v1.y += r1.y;
            }
            *(float2*)&O[(size_t)r*No + c] = v0;
            *(float2*)&O[(size_t)(r+8)*No + c] = v1;
        }
    }
}

// ---------------- RoPE in-place on q and k parts of fused qkv [M, 3C] ----------------
__global__ void k_rope(float* __restrict__ qkv)
{
    int idx = blockIdx.x * blockDim.x + threadIdx.x;
    if (idx >= MM*NHH*32) return;
    int i  = idx & 31;
    int hh = (idx >> 5) & (NHH - 1);
    int m  = idx >> 9;
    int t  = m & (TT - 1);
    float freq = __expf(-(float)i * 0.2878231366f);
    float ang = (float)t * freq;
    float s, c;
    __sincosf(ang, &s, &c);
    size_t qb = (size_t)m*C3 + hh*DHH + i;
    float q1 = qkv[qb], q2 = qkv[qb + 32];
    qkv[qb]      = q1*c - q2*s;
    qkv[qb + 32] = q2*c + q1*s;
    size_t kb = qb + CC;
    float k1 = qkv[kb], k2 = qkv[kb + 32];
    qkv[kb]      = k1*c - k2*s;
    qkv[kb + 32] = k2*c + k1*s;
}

// ---------------- Flash attention (fp32, 64x64 tiles, online softmax) ----------------
// Writes output directly as bf16 hi/lo (feeds the o-proj GEMM).
#define ATTN_SMEM (4*64*68*4)

__global__ void __launch_bounds__(256) k_attn(const float* __restrict__ qkv,
                                              __nv_bfloat16* __restrict__ ohi,
                                              __nv_bfloat16* __restrict__ olo)
{
    extern __shared__ float sm[];
    float (*Qs)[68] = (float(*)[68])(sm);
    float (*Ks)[68] = (float(*)[68])(sm + 64*68);
    float (*Vs)[68] = (float(*)[68])(sm + 2*64*68);
    float (*Ps)[68] = (float(*)[68])(sm + 3*64*68);

    const int bh = blockIdx.y;
    const int b = bh / NHH, hh = bh % NHH;
    const int qt = gridDim.x - 1 - blockIdx.x;
    const int t0 = qt * 64;
    const int tid = threadIdx.x;
    const int tx = tid & 15, ty = tid >> 4;
    const float scale = 0.125f;

    {
        int r = tid >> 2, d0 = (tid & 3) * 16;
        const float* src = qkv + ((size_t)(b*TT + t0 + r))*C3 + hh*DHH + d0;
        #pragma unroll
        for (int v = 0; v < 4; v++) {
            float4 f = *(const float4*)(src + v*4);
            Qs[d0+v*4+0][r] = f.x*scale; Qs[d0+v*4+1][r] = f.y*scale;
            Qs[d0+v*4+2][r] = f.z*scale; Qs[d0+v*4+3][r] = f.w*scale;
        }
    }

    float accO[4][4];
    float mrow[4], lrow[4];
    #pragma unroll
    for (int i = 0; i < 4; i++) {
        mrow[i] = -1e30f; lrow[i] = 0.f;
        #pragma unroll
        for (int j = 0; j < 4; j++) accO[i][j] = 0.f;
    }

    const int nst = qt + 1;
    for (int st = 0; st < nst; st++) {
        int s0 = st * 64;
        {
            int r = tid >> 2, d0 = (tid & 3) * 16;
            const float* kp = qkv + ((size_t)(b*TT + s0 + r))*C3 + CC + hh*DHH + d0;
            const float* vp = kp + CC;
            #pragma unroll
            for (int v = 0; v < 4; v++) {
                float4 f = *(const float4*)(kp + v*4);
                Ks[d0+v*4+0][r] = f.x; Ks[d0+v*4+1][r] = f.y;
                Ks[d0+v*4+2][r] = f.z; Ks[d0+v*4+3][r] = f.w;
                *(float4*)&Vs[r][d0+v*4] = *(const float4*)(vp + v*4);
            }
        }
        __syncthreads();

        float s[4][4] = {{0,0,0,0},{0,0,0,0},{0,0,0,0},{0,0,0,0}};
        #pragma unroll
        for (int d = 0; d < DHH; d++) {
            float4 qa = *(const float4*)&Qs[d][ty<<2];
            float4 kb = *(const float4*)&Ks[d][tx<<2];
            s[0][0]+=qa.x*kb.x; s[0][1]+=qa.x*kb.y; s[0][2]+=qa.x*kb.z; s[0][3]+=qa.x*kb.w;
            s[1][0]+=qa.y*kb.x; s[1][1]+=qa.y*kb.y; s[1][2]+=qa.y*kb.z; s[1][3]+=qa.y*kb.w;
            s[2][0]+=qa.z*kb.x; s[2][1]+=qa.z*kb.y; s[2][2]+=qa.z*kb.z; s[2][3]+=qa.z*kb.w;
            s[3][0]+=qa.w*kb.x; s[3][1]+=qa.w*kb.y; s[3][2]+=qa.w*kb.z; s[3][3]+=qa.w*kb.w;
        }
        if (st == nst - 1) {
            #pragma unroll
            for (int i = 0; i < 4; i++)
                #pragma unroll
                for (int j = 0; j < 4; j++)
                    if ((tx<<2)+j > (ty<<2)+i) s[i][j] = -1e30f;
        }
        #pragma unroll
        for (int i = 0; i < 4; i++) {
            float rmax = fmaxf(fmaxf(s[i][0], s[i][1]), fmaxf(s[i][2], s[i][3]));
            #pragma unroll
            for (int o = 1; o < 16; o <<= 1)
                rmax = fmaxf(rmax, __shfl_xor_sync(0xffffffffu, rmax, o));
            float mn = fmaxf(mrow[i], rmax);
            float corr = __expf(mrow[i] - mn);
            float rs = 0.f;
            #pragma unroll
            for (int j = 0; j < 4; j++) { s[i][j] = __expf(s[i][j] - mn); rs += s[i][j]; }
            #pragma unroll
            for (int o = 1; o < 16; o <<= 1)
                rs += __shfl_xor_sync(0xffffffffu, rs, o);
            lrow[i] = lrow[i]*corr + rs;
            mrow[i] = mn;
            #pragma unroll
            for (int j = 0; j < 4; j++) accO[i][j] *= corr;
            *(float4*)&Ps[(ty<<2)+i][tx<<2] = make_float4(s[i][0], s[i][1], s[i][2], s[i][3]);
        }
        __syncthreads();

        #pragma unroll
        for (int ss = 0; ss < 64; ss++) {
            float4 vv = *(const float4*)&Vs[ss][tx<<2];
            #pragma unroll
            for (int i = 0; i < 4; i++) {
                float p = Ps[(ty<<2)+i][ss];
                accO[i][0] += p*vv.x; accO[i][1] += p*vv.y;
                accO[i][2] += p*vv.z; accO[i][3] += p*vv.w;
            }
        }
        __syncthreads();
    }

    // write O (normalized) as bf16 hi/lo
    #pragma unroll
    for (int i = 0; i < 4; i++) {
        float inv = 1.f / lrow[i];
        size_t off = ((size_t)(b*TT + t0 + (ty<<2) + i))*CC + hh*DHH + (tx<<2);
        __nv_bfloat16 h4[4], l4[4];
        split1(accO[i][0]*inv, h4[0], l4[0]);
        split1(accO[i][1]*inv, h4[1], l4[1]);
        split1(accO[i][2]*inv, h4[2], l4[2]);
        split1(accO[i][3]*inv, h4[3], l4[3]);
        *(uint2*)(ohi + off) = *(uint2*)h4;
        *(uint2*)(olo + off) = *(uint2*)l4;
    }
}

// ---------------- launcher ----------------
extern "C" void kernel_launch(void* const* d_in, const int* in_sizes, int n_in,
                              void* d_out, int out_size)
{
    const float* x    = (const float*)d_in[0];
    const float* w_in = (const float*)d_in[1];
    const float* wq   = (const float*)d_in[2];
    const float* wkv  = (const float*)d_in[3];
    const float* wo   = (const float*)d_in[4];
    const float* w1   = (const float*)d_in[5];
    const float* w2   = (const float*)d_in[6];
    const float* w3   = (const float*)d_in[7];
    const float* g1   = (const float*)d_in[8];
    const float* g2   = (const float*)d_in[9];
    const float* gf   = (const float*)d_in[10];
    float* out = (float*)d_out;

    float *h, *qkv, *f12;
    __nv_bfloat16 *ah, *al;
    __nv_bfloat16 *wq_h, *wq_l, *wkv_h, *wkv_l, *wo_h, *wo_l;
    __nv_bfloat16 *w1_h, *w1_l, *w2_h, *w2_l, *w3_h, *w3_l;
    cudaGetSymbolAddress((void**)&h,   g_h);
    cudaGetSymbolAddress((void**)&qkv, g_qkv);
    cudaGetSymbolAddress((void**)&f12, g_f12);
    cudaGetSymbolAddress((void**)&ah,  g_ah);
    cudaGetSymbolAddress((void**)&al,  g_al);
    cudaGetSymbolAddress((void**)&wq_h,  g_wq_h);  cudaGetSymbolAddress((void**)&wq_l,  g_wq_l);
    cudaGetSymbolAddress((void**)&wkv_h, g_wkv_h); cudaGetSymbolAddress((void**)&wkv_l, g_wkv_l);
    cudaGetSymbolAddress((void**)&wo_h,  g_wo_h);  cudaGetSymbolAddress((void**)&wo_l,  g_wo_l);
    cudaGetSymbolAddress((void**)&w1_h,  g_w1_h);  cudaGetSymbolAddress((void**)&w1_l,  g_w1_l);
    cudaGetSymbolAddress((void**)&w2_h,  g_w2_h);  cudaGetSymbolAddress((void**)&w2_l,  g_w2_l);
    cudaGetSymbolAddress((void**)&w3_h,  g_w3_h);  cudaGetSymbolAddress((void**)&w3_l,  g_w3_l);

    cudaFuncSetAttribute((const void*)k_attn,
                         cudaFuncAttributeMaxDynamicSharedMemorySize, ATTN_SMEM);
    cudaFuncSetAttribute((const void*)k_mma<0>,
                         cudaFuncAttributeMaxDynamicSharedMemorySize, MMA_SMEM);
    cudaFuncSetAttribute((const void*)k_mma<1>,
                         cudaFuncAttributeMaxDynamicSharedMemorySize, MMA_SMEM);

    // ---- weight split (all layers, once per launch) ----
    {
        int n;
        n = LL*CC*CC;    k_split<<<(n/4+255)/256, 256>>>(wq,  wq_h,  wq_l,  n);
        n = LL*2*CC*CC;  k_split<<<(n/4+255)/256, 256>>>(wkv, wkv_h, wkv_l, n);
        n = LL*CC*CC;    k_split<<<(n/4+255)/256, 256>>>(wo,  wo_h,  wo_l,  n);
        n = LL*HF*CC;    k_split<<<(n/4+255)/256, 256>>>(w1,  w1_h,  w1_l,  n);
        n = LL*HF*CC;    k_split<<<(n/4+255)/256, 256>>>(w2,  w2_h,  w2_l,  n);
        n = LL*CC*HF;    k_split<<<(n/4+255)/256, 256>>>(w3,  w3_h,  w3_l,  n);
    }

    k_inproj<<<MM, 256>>>(x, w_in, h);

    for (int l = 0; l < LL; l++) {
        __nv_bfloat16* wq_hl  = wq_h  + (size_t)l*CC*CC;
        __nv_bfloat16* wq_ll  = wq_l  + (size_t)l*CC*CC;
        __nv_bfloat16* wkv_hl = wkv_h + (size_t)l*2*CC*CC;
        __nv_bfloat16* wkv_ll = wkv_l + (size_t)l*2*CC*CC;
        __nv_bfloat16* wo_hl  = wo_h  + (size_t)l*CC*CC;
        __nv_bfloat16* wo_ll  = wo_l  + (size_t)l*CC*CC;
        __nv_bfloat16* w1_hl  = w1_h  + (size_t)l*HF*CC;
        __nv_bfloat16* w1_ll  = w1_l  + (size_t)l*HF*CC;
        __nv_bfloat16* w2_hl  = w2_h  + (size_t)l*HF*CC;
        __nv_bfloat16* w2_ll  = w2_l  + (size_t)l*HF*CC;
        __nv_bfloat16* w3_hl  = w3_h  + (size_t)l*CC*HF;
        __nv_bfloat16* w3_ll  = w3_l  + (size_t)l*CC*HF;

        // ---- attention block ----
        k_rms_split<<<MM, 256>>>(h, g1 + l*CC, ah, al);
        k_mma<0><<<dim3(C3/128, MM/128), 256, MMA_SMEM>>>(
            ah, al, wq_hl, wq_ll, wkv_hl, wkv_ll, CC, nullptr, qkv, C3, CC);
        k_rope<<<(MM*NHH*32)/256, 256>>>(qkv);
        k_attn<<<dim3(TT/64, BB*NHH), 256, ATTN_SMEM>>>(qkv, ah, al);
        k_mma<1><<<dim3(CC/128, MM/128), 256, MMA_SMEM>>>(
            ah, al, wo_hl, wo_ll, nullptr, nullptr, 0, h, h, CC, CC);

        // ---- MLP block ----
        k_rms_split<<<MM, 256>>>(h, g2 + l*CC, ah, al);
        k_mma<0><<<dim3(HF2/128, MM/128), 256, MMA_SMEM>>>(
            ah, al, w1_hl, w1_ll, w2_hl, w2_ll, HF, nullptr, f12, HF2, CC);
        k_silu_split<<<(MM*HF/4+255)/256, 256>>>(f12, ah, al);
        k_mma<1><<<dim3(CC/128, MM/128), 256, MMA_SMEM>>>(
            ah, al, w3_hl, w3_ll, nullptr, nullptr, 0, h, h, CC, HF);
    }

    k_rms<<<MM, 256>>>(h, gf, out);
}

// round 7
// speedup vs baseline: 2.8573x; 1.3269x over previous
#include <cuda_runtime.h>
#include <cuda_bf16.h>
#include <math.h>
#include <stddef.h>
#include <stdint.h>

#define BB 2
#define TT 1024
#define CC 1024
#define NHH 16
#define DHH 64
#define LL 4
#define HF 2816
#define FT 9
#define MM (BB*TT)
#define C3 (3*CC)
#define HF2 (2*HF)

// ---------------- scratch (static device globals; no allocation) ----------------
__device__ __align__(256) float g_h  [MM*CC];
__device__ __align__(256) float g_qkv[MM*C3];
__device__ __align__(256) float g_f12[(size_t)MM*HF2];

__device__ __align__(256) __nv_bfloat16 g_ah[(size_t)MM*HF];
__device__ __align__(256) __nv_bfloat16 g_al[(size_t)MM*HF];

// attention operand buffers, bf16 hi/lo, layout [m][h*64+d]
__device__ __align__(256) __nv_bfloat16 g_qh2[MM*CC], g_ql2[MM*CC];
__device__ __align__(256) __nv_bfloat16 g_kh2[MM*CC], g_kl2[MM*CC];
__device__ __align__(256) __nv_bfloat16 g_vh2[MM*CC], g_vl2[MM*CC];

// bf16 hi/lo weights (all layers)
__device__ __align__(256) __nv_bfloat16 g_wq_h [(size_t)LL*CC*CC];
__device__ __align__(256) __nv_bfloat16 g_wq_l [(size_t)LL*CC*CC];
__device__ __align__(256) __nv_bfloat16 g_wkv_h[(size_t)LL*2*CC*CC];
__device__ __align__(256) __nv_bfloat16 g_wkv_l[(size_t)LL*2*CC*CC];
__device__ __align__(256) __nv_bfloat16 g_wo_h [(size_t)LL*CC*CC];
__device__ __align__(256) __nv_bfloat16 g_wo_l [(size_t)LL*CC*CC];
__device__ __align__(256) __nv_bfloat16 g_w1_h [(size_t)LL*HF*CC];
__device__ __align__(256) __nv_bfloat16 g_w1_l [(size_t)LL*HF*CC];
__device__ __align__(256) __nv_bfloat16 g_w2_h [(size_t)LL*HF*CC];
__device__ __align__(256) __nv_bfloat16 g_w2_l [(size_t)LL*HF*CC];
__device__ __align__(256) __nv_bfloat16 g_w3_h [(size_t)LL*CC*HF];
__device__ __align__(256) __nv_bfloat16 g_w3_l [(size_t)LL*CC*HF];

// ---------------- helpers ----------------
__device__ __forceinline__ void split1(float v, __nv_bfloat16& h, __nv_bfloat16& l)
{
    h = __float2bfloat16(v);
    l = __float2bfloat16(v - __bfloat162float(h));
}
__device__ __forceinline__ uint32_t packbf(__nv_bfloat16 a, __nv_bfloat16 b)
{
    uint16_t ua = *(uint16_t*)&a, ub = *(uint16_t*)&b;
    return (uint32_t)ua | ((uint32_t)ub << 16);
}
__device__ __forceinline__ void split_pack2(float x, float y, uint32_t& hi, uint32_t& lo)
{
    __nv_bfloat16 xh, xl, yh, yl;
    split1(x, xh, xl); split1(y, yh, yl);
    hi = packbf(xh, yh);
    lo = packbf(xl, yl);
}

__global__ void k_split(const float* __restrict__ x, __nv_bfloat16* __restrict__ hi,
                        __nv_bfloat16* __restrict__ lo, int n)
{
    int i = (blockIdx.x*256 + threadIdx.x)*4;
    if (i >= n) return;
    float4 v = *(const float4*)(x + i);
    __nv_bfloat16 h4[4], l4[4];
    split1(v.x, h4[0], l4[0]); split1(v.y, h4[1], l4[1]);
    split1(v.z, h4[2], l4[2]); split1(v.w, h4[3], l4[3]);
    *(uint2*)(hi + i) = *(uint2*)h4;
    *(uint2*)(lo + i) = *(uint2*)l4;
}

__global__ void k_silu_split(const float* __restrict__ f12,
                             __nv_bfloat16* __restrict__ hi,
                             __nv_bfloat16* __restrict__ lo)
{
    int i = (blockIdx.x*256 + threadIdx.x)*4;
    if (i >= MM*HF) return;
    int m = i / HF, j = i - m*HF;
    float4 a = *(const float4*)&f12[(size_t)m*HF2 + j];
    float4 b = *(const float4*)&f12[(size_t)m*HF2 + HF + j];
    float v0 = a.x / (1.f + __expf(-a.x)) * b.x;
    float v1 = a.y / (1.f + __expf(-a.y)) * b.y;
    float v2 = a.z / (1.f + __expf(-a.z)) * b.z;
    float v3 = a.w / (1.f + __expf(-a.w)) * b.w;
    __nv_bfloat16 h4[4], l4[4];
    split1(v0, h4[0], l4[0]); split1(v1, h4[1], l4[1]);
    split1(v2, h4[2], l4[2]); split1(v3, h4[3], l4[3]);
    *(uint2*)(hi + i) = *(uint2*)h4;
    *(uint2*)(lo + i) = *(uint2*)l4;
}

__global__ void k_inproj(const float* __restrict__ x, const float* __restrict__ w_in,
                         float* __restrict__ h)
{
    int m = blockIdx.x;
    __shared__ float xs[FT];
    if (threadIdx.x < FT) xs[threadIdx.x] = x[m*FT + threadIdx.x];
    __syncthreads();
    for (int c = threadIdx.x; c < CC; c += blockDim.x) {
        float acc = 0.f;
        #pragma unroll
        for (int f = 0; f < FT; f++) acc += xs[f] * w_in[c*FT + f];
        h[(size_t)m*CC + c] = acc;
    }
}

__global__ void k_rms(const float* __restrict__ in, const float* __restrict__ g,
                      float* __restrict__ out)
{
    int m = blockIdx.x;
    const float* row = in + (size_t)m*CC;
    float4 v = *(const float4*)(row + threadIdx.x*4);
    float ss = v.x*v.x + v.y*v.y + v.z*v.z + v.w*v.w;
    __shared__ float red[8];
    #pragma unroll
    for (int o = 16; o; o >>= 1) ss += __shfl_xor_sync(0xffffffffu, ss, o);
    if ((threadIdx.x & 31) == 0) red[threadIdx.x >> 5] = ss;
    __syncthreads();
    if (threadIdx.x < 8) {
        float t = red[threadIdx.x];
        #pragma unroll
        for (int o = 4; o; o >>= 1) t += __shfl_xor_sync(0xffu, t, o);
        if (threadIdx.x == 0) red[0] = t;
    }
    __syncthreads();
    float r = rsqrtf(red[0] * (1.0f/CC) + 1e-5f);
    int c = threadIdx.x*4;
    const float4 gv = *(const float4*)(g + c);
    float4 o = make_float4(v.x*r*gv.x, v.y*r*gv.y, v.z*r*gv.z, v.w*r*gv.w);
    *(float4*)(out + (size_t)m*CC + c) = o;
}

__global__ void k_rms_split(const float* __restrict__ in, const float* __restrict__ g,
                            __nv_bfloat16* __restrict__ hi, __nv_bfloat16* __restrict__ lo)
{
    int m = blockIdx.x;
    const float* row = in + (size_t)m*CC;
    float4 v = *(const float4*)(row + threadIdx.x*4);
    float ss = v.x*v.x + v.y*v.y + v.z*v.z + v.w*v.w;
    __shared__ float red[8];
    #pragma unroll
    for (int o = 16; o; o >>= 1) ss += __shfl_xor_sync(0xffffffffu, ss, o);
    if ((threadIdx.x & 31) == 0) red[threadIdx.x >> 5] = ss;
    __syncthreads();
    if (threadIdx.x < 8) {
        float t = red[threadIdx.x];
        #pragma unroll
        for (int o = 4; o; o >>= 1) t += __shfl_xor_sync(0xffu, t, o);
        if (threadIdx.x == 0) red[0] = t;
    }
    __syncthreads();
    float r = rsqrtf(red[0] * (1.0f/CC) + 1e-5f);
    int c = threadIdx.x*4;
    const float4 gv = *(const float4*)(g + c);
    __nv_bfloat16 h4[4], l4[4];
    split1(v.x*r*gv.x, h4[0], l4[0]); split1(v.y*r*gv.y, h4[1], l4[1]);
    split1(v.z*r*gv.z, h4[2], l4[2]); split1(v.w*r*gv.w, h4[3], l4[3]);
    *(uint2*)(hi + (size_t)m*CC + c) = *(uint2*)h4;
    *(uint2*)(lo + (size_t)m*CC + c) = *(uint2*)l4;
}

// ---------------- MMA building blocks ----------------
#define LDSM4(r, addr) \
    asm volatile("ldmatrix.sync.aligned.m8n8.x4.shared.b16 {%0,%1,%2,%3}, [%4];" \
        : "=r"((r)[0]), "=r"((r)[1]), "=r"((r)[2]), "=r"((r)[3]) : "r"(addr))
#define LDSM4T(r, addr) \
    asm volatile("ldmatrix.sync.aligned.m8n8.x4.trans.shared.b16 {%0,%1,%2,%3}, [%4];" \
        : "=r"((r)[0]), "=r"((r)[1]), "=r"((r)[2]), "=r"((r)[3]) : "r"(addr))
#define MMA16816(d, a, b0, b1) \
    asm volatile("mma.sync.aligned.m16n8k16.row.col.f32.bf16.bf16.f32 " \
        "{%0,%1,%2,%3}, {%4,%5,%6,%7}, {%8,%9}, {%0,%1,%2,%3};" \
        : "+f"((d)[0]), "+f"((d)[1]), "+f"((d)[2]), "+f"((d)[3]) \
        : "r"((a)[0]), "r"((a)[1]), "r"((a)[2]), "r"((a)[3]), "r"(b0), "r"(b1))

// ---------------- bf16-split tensor-core GEMM (128x128x32, 8 warps) ----------------
#define LDT 40
#define STG_B (128*LDT*2)
#define SS_B  (4*STG_B)
#define MMA_SMEM (3*SS_B)

__device__ __forceinline__ void stage_load(uint32_t s_base, const __nv_bfloat16* g_base,
                                           int K, int k0)
{
    int tid = threadIdx.x;
    #pragma unroll
    for (int i = 0; i < 2; i++) {
        int c = tid + i*256;
        int row = c >> 2, col = c & 3;
        uint32_t dst = s_base + (uint32_t)(row*LDT + col*8)*2;
        const __nv_bfloat16* src = g_base + (size_t)row*K + k0 + col*8;
        asm volatile("cp.async.cg.shared.global [%0], [%1], 16;" :: "r"(dst), "l"(src));
    }
}

template<int MODE>   // 0: O=acc ; 1: O=R+acc
__global__ void __launch_bounds__(256) k_mma(
    const __nv_bfloat16* __restrict__ Ah, const __nv_bfloat16* __restrict__ Al,
    const __nv_bfloat16* __restrict__ W0h, const __nv_bfloat16* __restrict__ W0l,
    const __nv_bfloat16* W1h, const __nv_bfloat16* W1l, int nsplit,
    const float* R, float* O, int No, int K)
{
    extern __shared__ __nv_bfloat16 smem[];
    const int m0 = blockIdx.y << 7, n0 = blockIdx.x << 7;

    const __nv_bfloat16 *Wh, *Wl;
    if (W1h != nullptr && n0 >= nsplit) {
        Wh = W1h + (size_t)(n0 - nsplit)*K;
        Wl = W1l + (size_t)(n0 - nsplit)*K;
    } else {
        Wh = W0h + (size_t)n0*K;
        Wl = W0l + (size_t)n0*K;
    }
    const __nv_bfloat16* Am_h = Ah + (size_t)m0*K;
    const __nv_bfloat16* Am_l = Al + (size_t)m0*K;

    uint32_t s0 = (uint32_t)__cvta_generic_to_shared(smem);
    const int nt = K >> 5;

    #pragma unroll
    for (int p = 0; p < 2; p++) {
        uint32_t sb = s0 + p*SS_B;
        stage_load(sb,           Am_h, K, p*32);
        stage_load(sb + STG_B,   Am_l, K, p*32);
        stage_load(sb + 2*STG_B, Wh,   K, p*32);
        stage_load(sb + 3*STG_B, Wl,   K, p*32);
        asm volatile("cp.async.commit_group;");
    }

    const int lane = threadIdx.x & 31, wid = threadIdx.x >> 5;
    const int wm = (wid & 3) << 5;
    const int wn = (wid >> 2) << 6;

    float acc[2][8][4];
    #pragma unroll
    for (int a = 0; a < 2; a++)
        #pragma unroll
        for (int b = 0; b < 8; b++)
            #pragma unroll
            for (int c = 0; c < 4; c++) acc[a][b][c] = 0.f;

    const int a_row_lane = (lane & 7) + ((lane >> 3) & 1)*8;
    const int a_kadd = (lane >> 4)*8;
    const int b_row_lane = (lane & 7) + ((lane >> 4) & 1)*8;
    const int b_kadd = ((lane >> 3) & 1)*8;

    for (int kt = 0; kt < nt; kt++) {
        asm volatile("cp.async.wait_group 1;");
        __syncthreads();
        uint32_t sb = s0 + (uint32_t)(kt % 3)*SS_B;

        #pragma unroll
        for (int ka = 0; ka < 2; ka++) {
            uint32_t ahr[2][4], alr[2][4];
            #pragma unroll
            for (int ma = 0; ma < 2; ma++) {
                uint32_t ad = sb + (uint32_t)(((wm + ma*16 + a_row_lane)*LDT
                                               + ka*16 + a_kadd) << 1);
                LDSM4(ahr[ma], ad);
                LDSM4(alr[ma], ad + STG_B);
            }
            #pragma unroll
            for (int nbp = 0; nbp < 4; nbp++) {
                uint32_t bd = sb + 2*STG_B + (uint32_t)(((wn + nbp*16 + b_row_lane)*LDT
                                                         + ka*16 + b_kadd) << 1);
                uint32_t bh4[4], bl4[4];
                LDSM4(bh4, bd);
                LDSM4(bl4, bd + STG_B);
                #pragma unroll
                for (int ma = 0; ma < 2; ma++) {
                    MMA16816(acc[ma][2*nbp],   ahr[ma], bh4[0], bh4[1]);
                    MMA16816(acc[ma][2*nbp],   ahr[ma], bl4[0], bl4[1]);
                    MMA16816(acc[ma][2*nbp],   alr[ma], bh4[0], bh4[1]);
                    MMA16816(acc[ma][2*nbp+1], ahr[ma], bh4[2], bh4[3]);
                    MMA16816(acc[ma][2*nbp+1], ahr[ma], bl4[2], bl4[3]);
                    MMA16816(acc[ma][2*nbp+1], alr[ma], bh4[2], bh4[3]);
                }
            }
        }

        int kn = kt + 2;
        if (kn < nt) {
            uint32_t sb2 = s0 + (uint32_t)(kn % 3)*SS_B;
            stage_load(sb2,           Am_h, K, kn*32);
            stage_load(sb2 + STG_B,   Am_l, K, kn*32);
            stage_load(sb2 + 2*STG_B, Wh,   K, kn*32);
            stage_load(sb2 + 3*STG_B, Wl,   K, kn*32);
        }
        asm volatile("cp.async.commit_group;");
    }

    const int quad = lane >> 2, tq = lane & 3;
    #pragma unroll
    for (int ma = 0; ma < 2; ma++) {
        #pragma unroll
        for (int nb = 0; nb < 8; nb++) {
            int r = m0 + wm + ma*16 + quad;
            int c = n0 + wn + nb*8 + tq*2;
            float2 v0 = make_float2(acc[ma][nb][0], acc[ma][nb][1]);
            float2 v1 = make_float2(acc[ma][nb][2], acc[ma][nb][3]);
            if (MODE == 1) {
                float2 r0 = *(const float2*)&R[(size_t)r*No + c];
                float2 r1 = *(const float2*)&R[(size_t)(r+8)*No + c];
                v0.x += r0.x; v0.y += r0.y;
                v1.x += r1.x; v1.y += r1.y;
            }
            *(float2*)&O[(size_t)r*No + c] = v0;
            *(float2*)&O[(size_t)(r+8)*No + c] = v1;
        }
    }
}

// ---------------- RoPE + split: qkv fp32 -> q/k/v bf16 hi/lo (q pre-scaled 1/8) ----------------
__global__ void k_rope_split(const float* __restrict__ qkv,
                             __nv_bfloat16* __restrict__ qh, __nv_bfloat16* __restrict__ ql,
                             __nv_bfloat16* __restrict__ kh, __nv_bfloat16* __restrict__ kl,
                             __nv_bfloat16* __restrict__ vh, __nv_bfloat16* __restrict__ vl)
{
    int idx = blockIdx.x * blockDim.x + threadIdx.x;
    if (idx >= MM*NHH*32) return;
    int i  = idx & 31;
    int hh = (idx >> 5) & (NHH - 1);
    int m  = idx >> 9;
    int t  = m & (TT - 1);
    float freq = __expf(-(float)i * 0.2878231366f);
    float ang = (float)t * freq;
    float s, c;
    __sincosf(ang, &s, &c);

    size_t src = (size_t)m*C3 + hh*DHH + i;
    size_t dst = (size_t)m*CC + hh*DHH + i;

    float q1 = qkv[src], q2 = qkv[src + 32];
    float qo1 = (q1*c - q2*s) * 0.125f;
    float qo2 = (q2*c + q1*s) * 0.125f;
    split1(qo1, qh[dst], ql[dst]);
    split1(qo2, qh[dst+32], ql[dst+32]);

    float k1 = qkv[src + CC], k2 = qkv[src + CC + 32];
    float ko1 = k1*c - k2*s;
    float ko2 = k2*c + k1*s;
    split1(ko1, kh[dst], kl[dst]);
    split1(ko2, kh[dst+32], kl[dst+32]);

    float v1 = qkv[src + 2*CC], v2 = qkv[src + 2*CC + 32];
    split1(v1, vh[dst], vl[dst]);
    split1(v2, vh[dst+32], vl[dst+32]);
}

// ---------------- tensor-core flash attention (64x64 tiles, bf16 split, online softmax) ----------------
// grid (TT/64, BB*NHH), 128 threads (4 warps; warp w owns q rows w*16..+15)
#define APITCH 72
#define ATILE (64*APITCH)
#define ATT_SMEM2 (6*ATILE*2)

__global__ void __launch_bounds__(128) k_attn_mma(
    const __nv_bfloat16* __restrict__ qh, const __nv_bfloat16* __restrict__ ql,
    const __nv_bfloat16* __restrict__ kh, const __nv_bfloat16* __restrict__ kl,
    const __nv_bfloat16* __restrict__ vh, const __nv_bfloat16* __restrict__ vl,
    __nv_bfloat16* __restrict__ ohi, __nv_bfloat16* __restrict__ olo)
{
    extern __shared__ __nv_bfloat16 smA[];
    const uint32_t sb = (uint32_t)__cvta_generic_to_shared(smA);
    const uint32_t oQh = 0, oQl = ATILE*2, oKh = 2*ATILE*2, oKl = 3*ATILE*2,
                   oVh = 4*ATILE*2, oVl = 5*ATILE*2;

    const int bh = blockIdx.y;
    const int b = bh >> 4, hh = bh & 15;
    const int qt = gridDim.x - 1 - blockIdx.x;
    const int t0 = qt * 64;
    const int tid = threadIdx.x;
    const int lane = tid & 31, w = tid >> 5;

    // ---- load Q tile (hi/lo) into smem ----
    {
        size_t gbase = ((size_t)(b*TT + t0))*CC + hh*DHH;
        #pragma unroll
        for (int j = 0; j < 4; j++) {
            int idx = tid + j*128;
            int row = idx >> 3, c8 = idx & 7;
            size_t go = gbase + (size_t)row*CC + c8*8;
            *(uint4*)&smA[(oQh>>1) + row*APITCH + c8*8] = *(const uint4*)(qh + go);
            *(uint4*)&smA[(oQl>>1) + row*APITCH + c8*8] = *(const uint4*)(ql + go);
        }
    }
    __syncthreads();

    // ---- Q fragments (register-resident) ----
    const int a_row = w*16 + (lane & 7) + ((lane >> 3) & 1)*8;
    const int a_kadd = (lane >> 4)*8;
    uint32_t qfh[4][4], qfl[4][4];
    #pragma unroll
    for (int kc = 0; kc < 4; kc++) {
        uint32_t ad = sb + oQh + (uint32_t)((a_row*APITCH + kc*16 + a_kadd) << 1);
        LDSM4(qfh[kc], ad);
        LDSM4(qfl[kc], ad + (oQl - oQh));
    }

    float accO[8][4];
    #pragma unroll
    for (int d = 0; d < 8; d++)
        #pragma unroll
        for (int c = 0; c < 4; c++) accO[d][c] = 0.f;
    float mA = -1e30f, mB = -1e30f, lA = 0.f, lB = 0.f;

    const int b_row = (lane & 7) + ((lane >> 4) & 1)*8;
    const int b_kadd = ((lane >> 3) & 1)*8;
    const int v_row = (lane & 7) + ((lane >> 3) & 1)*8;
    const int v_cadd = ((lane >> 4) & 1)*8;

    const int nst = qt + 1;
    for (int st = 0; st < nst; st++) {
        int s0 = st * 64;
        __syncthreads();
        {
            size_t gbase = ((size_t)(b*TT + s0))*CC + hh*DHH;
            #pragma unroll
            for (int j = 0; j < 4; j++) {
                int idx = tid + j*128;
                int row = idx >> 3, c8 = idx & 7;
                size_t go = gbase + (size_t)row*CC + c8*8;
                uint32_t so = row*APITCH + c8*8;
                *(uint4*)&smA[(oKh>>1) + so] = *(const uint4*)(kh + go);
                *(uint4*)&smA[(oKl>>1) + so] = *(const uint4*)(kl + go);
                *(uint4*)&smA[(oVh>>1) + so] = *(const uint4*)(vh + go);
                *(uint4*)&smA[(oVl>>1) + so] = *(const uint4*)(vl + go);
            }
        }
        __syncthreads();

        // ---- S = Q K^T (3-mma split) ----
        float sacc[8][4];
        #pragma unroll
        for (int nb = 0; nb < 8; nb++)
            #pragma unroll
            for (int c = 0; c < 4; c++) sacc[nb][c] = 0.f;

        #pragma unroll
        for (int kc = 0; kc < 4; kc++) {
            #pragma unroll
            for (int nbp = 0; nbp < 4; nbp++) {
                uint32_t kd = sb + oKh + (uint32_t)(((nbp*16 + b_row)*APITCH
                                                    + kc*16 + b_kadd) << 1);
                uint32_t bh4[4], bl4[4];
                LDSM4(bh4, kd);
                LDSM4(bl4, kd + (oKl - oKh));
                MMA16816(sacc[2*nbp],   qfh[kc], bh4[0], bh4[1]);
                MMA16816(sacc[2*nbp],   qfh[kc], bl4[0], bl4[1]);
                MMA16816(sacc[2*nbp],   qfl[kc], bh4[0], bh4[1]);
                MMA16816(sacc[2*nbp+1], qfh[kc], bh4[2], bh4[3]);
                MMA16816(sacc[2*nbp+1], qfh[kc], bl4[2], bl4[3]);
                MMA16816(sacc[2*nbp+1], qfl[kc], bh4[2], bh4[3]);
            }
        }

        // causal mask on diagonal tile
        if (st == qt) {
            #pragma unroll
            for (int nb = 0; nb < 8; nb++) {
                #pragma unroll
                for (int c = 0; c < 4; c++) {
                    int col = nb*8 + (lane & 3)*2 + (c & 1);
                    int row = w*16 + (lane >> 2) + ((c >> 1) ? 8 : 0);
                    if (col > row) sacc[nb][c] = -1e30f;
                }
            }
        }

        // ---- online softmax (rows lane>>2 and +8) ----
        float mxA = -1e30f, mxB = -1e30f;
        #pragma unroll
        for (int nb = 0; nb < 8; nb++) {
            mxA = fmaxf(mxA, fmaxf(sacc[nb][0], sacc[nb][1]));
            mxB = fmaxf(mxB, fmaxf(sacc[nb][2], sacc[nb][3]));
        }
        #pragma unroll
        for (int o = 1; o < 4; o <<= 1) {
            mxA = fmaxf(mxA, __shfl_xor_sync(0xffffffffu, mxA, o));
            mxB = fmaxf(mxB, __shfl_xor_sync(0xffffffffu, mxB, o));
        }
        float mnA = fmaxf(mA, mxA), mnB = fmaxf(mB, mxB);
        float corrA = __expf(mA - mnA), corrB = __expf(mB - mnB);
        float sA = 0.f, sBv = 0.f;
        #pragma unroll
        for (int nb = 0; nb < 8; nb++) {
            sacc[nb][0] = __expf(sacc[nb][0] - mnA);
            sacc[nb][1] = __expf(sacc[nb][1] - mnA);
            sacc[nb][2] = __expf(sacc[nb][2] - mnB);
            sacc[nb][3] = __expf(sacc[nb][3] - mnB);
            sA  += sacc[nb][0] + sacc[nb][1];
            sBv += sacc[nb][2] + sacc[nb][3];
        }
        #pragma unroll
        for (int o = 1; o < 4; o <<= 1) {
            sA  += __shfl_xor_sync(0xffffffffu, sA, o);
            sBv += __shfl_xor_sync(0xffffffffu, sBv, o);
        }
        lA = lA*corrA + sA;  mA = mnA;
        lB = lB*corrB + sBv; mB = mnB;
        #pragma unroll
        for (int d = 0; d < 8; d++) {
            accO[d][0] *= corrA; accO[d][1] *= corrA;
            accO[d][2] *= corrB; accO[d][3] *= corrB;
        }

        // ---- accO += P V ----
        #pragma unroll
        for (int kc = 0; kc < 4; kc++) {
            uint32_t ph[4], pl[4];
            split_pack2(sacc[2*kc][0],   sacc[2*kc][1],   ph[0], pl[0]);
            split_pack2(sacc[2*kc][2],   sacc[2*kc][3],   ph[1], pl[1]);
            split_pack2(sacc[2*kc+1][0], sacc[2*kc+1][1], ph[2], pl[2]);
            split_pack2(sacc[2*kc+1][2], sacc[2*kc+1][3], ph[3], pl[3]);
            #pragma unroll
            for (int dbp = 0; dbp < 4; dbp++) {
                uint32_t vd = sb + oVh + (uint32_t)(((kc*16 + v_row)*APITCH
                                                    + dbp*16 + v_cadd) << 1);
                uint32_t vh4[4], vl4[4];
                LDSM4T(vh4, vd);
                LDSM4T(vl4, vd + (oVl - oVh));
                MMA16816(accO[2*dbp],   ph, vh4[0], vh4[1]);
                MMA16816(accO[2*dbp],   ph, vl4[0], vl4[1]);
                MMA16816(accO[2*dbp],   pl, vh4[0], vh4[1]);
                MMA16816(accO[2*dbp+1], ph, vh4[2], vh4[3]);
                MMA16816(accO[2*dbp+1], ph, vl4[2], vl4[3]);
                MMA16816(accO[2*dbp+1], pl, vh4[2], vh4[3]);
            }
        }
    }

    // ---- epilogue: normalize, split, store ----
    float invA = 1.f / lA, invB = 1.f / lB;
    int rowA = t0 + w*16 + (lane >> 2);
    size_t baseA = (size_t)(b*TT + rowA)*CC + hh*DHH + (lane & 3)*2;
    size_t baseB = baseA + 8*CC;
    #pragma unroll
    for (int db = 0; db < 8; db++) {
        uint32_t hA, lA2, hB, lB2;
        split_pack2(accO[db][0]*invA, accO[db][1]*invA, hA, lA2);
        split_pack2(accO[db][2]*invB, accO[db][3]*invB, hB, lB2);
        *(uint32_t*)(ohi + baseA + db*8) = hA;
        *(uint32_t*)(olo + baseA + db*8) = lA2;
        *(uint32_t*)(ohi + baseB + db*8) = hB;
        *(uint32_t*)(olo + baseB + db*8) = lB2;
    }
}

// ---------------- launcher ----------------
extern "C" void kernel_launch(void* const* d_in, const int* in_sizes, int n_in,
                              void* d_out, int out_size)
{
    const float* x    = (const float*)d_in[0];
    const float* w_in = (const float*)d_in[1];
    const float* wq   = (const float*)d_in[2];
    const float* wkv  = (const float*)d_in[3];
    const float* wo   = (const float*)d_in[4];
    const float* w1   = (const float*)d_in[5];
    const float* w2   = (const float*)d_in[6];
    const float* w3   = (const float*)d_in[7];
    const float* g1   = (const float*)d_in[8];
    const float* g2   = (const float*)d_in[9];
    const float* gf   = (const float*)d_in[10];
    float* out = (float*)d_out;

    float *h, *qkv, *f12;
    __nv_bfloat16 *ah, *al, *qh2, *ql2, *kh2, *kl2, *vh2, *vl2;
    __nv_bfloat16 *wq_h, *wq_l, *wkv_h, *wkv_l, *wo_h, *wo_l;
    __nv_bfloat16 *w1_h, *w1_l, *w2_h, *w2_l, *w3_h, *w3_l;
    cudaGetSymbolAddress((void**)&h,   g_h);
    cudaGetSymbolAddress((void**)&qkv, g_qkv);
    cudaGetSymbolAddress((void**)&f12, g_f12);
    cudaGetSymbolAddress((void**)&ah,  g_ah);
    cudaGetSymbolAddress((void**)&al,  g_al);
    cudaGetSymbolAddress((void**)&qh2, g_qh2); cudaGetSymbolAddress((void**)&ql2, g_ql2);
    cudaGetSymbolAddress((void**)&kh2, g_kh2); cudaGetSymbolAddress((void**)&kl2, g_kl2);
    cudaGetSymbolAddress((void**)&vh2, g_vh2); cudaGetSymbolAddress((void**)&vl2, g_vl2);
    cudaGetSymbolAddress((void**)&wq_h,  g_wq_h);  cudaGetSymbolAddress((void**)&wq_l,  g_wq_l);
    cudaGetSymbolAddress((void**)&wkv_h, g_wkv_h); cudaGetSymbolAddress((void**)&wkv_l, g_wkv_l);
    cudaGetSymbolAddress((void**)&wo_h,  g_wo_h);  cudaGetSymbolAddress((void**)&wo_l,  g_wo_l);
    cudaGetSymbolAddress((void**)&w1_h,  g_w1_h);  cudaGetSymbolAddress((void**)&w1_l,  g_w1_l);
    cudaGetSymbolAddress((void**)&w2_h,  g_w2_h);  cudaGetSymbolAddress((void**)&w2_l,  g_w2_l);
    cudaGetSymbolAddress((void**)&w3_h,  g_w3_h);  cudaGetSymbolAddress((void**)&w3_l,  g_w3_l);

    cudaFuncSetAttribute((const void*)k_attn_mma,
                         cudaFuncAttributeMaxDynamicSharedMemorySize, ATT_SMEM2);
    cudaFuncSetAttribute((const void*)k_mma<0>,
                         cudaFuncAttributeMaxDynamicSharedMemorySize, MMA_SMEM);
    cudaFuncSetAttribute((const void*)k_mma<1>,
                         cudaFuncAttributeMaxDynamicSharedMemorySize, MMA_SMEM);

    // weight split (once per launch)
    {
        int n;
        n = LL*CC*CC;    k_split<<<(n/4+255)/256, 256>>>(wq,  wq_h,  wq_l,  n);
        n = LL*2*CC*CC;  k_split<<<(n/4+255)/256, 256>>>(wkv, wkv_h, wkv_l, n);
        n = LL*CC*CC;    k_split<<<(n/4+255)/256, 256>>>(wo,  wo_h,  wo_l,  n);
        n = LL*HF*CC;    k_split<<<(n/4+255)/256, 256>>>(w1,  w1_h,  w1_l,  n);
        n = LL*HF*CC;    k_split<<<(n/4+255)/256, 256>>>(w2,  w2_h,  w2_l,  n);
        n = LL*CC*HF;    k_split<<<(n/4+255)/256, 256>>>(w3,  w3_h,  w3_l,  n);
    }

    k_inproj<<<MM, 256>>>(x, w_in, h);

    for (int l = 0; l < LL; l++) {
        __nv_bfloat16* wq_hl  = wq_h  + (size_t)l*CC*CC;
        __nv_bfloat16* wq_ll  = wq_l  + (size_t)l*CC*CC;
        __nv_bfloat16* wkv_hl = wkv_h + (size_t)l*2*CC*CC;
        __nv_bfloat16* wkv_ll = wkv_l + (size_t)l*2*CC*CC;
        __nv_bfloat16* wo_hl  = wo_h  + (size_t)l*CC*CC;
        __nv_bfloat16* wo_ll  = wo_l  + (size_t)l*CC*CC;
        __nv_bfloat16* w1_hl  = w1_h  + (size_t)l*HF*CC;
        __nv_bfloat16* w1_ll  = w1_l  + (size_t)l*HF*CC;
        __nv_bfloat16* w2_hl  = w2_h  + (size_t)l*HF*CC;
        __nv_bfloat16* w2_ll  = w2_l  + (size_t)l*HF*CC;
        __nv_bfloat16* w3_hl  = w3_h  + (size_t)l*CC*HF;
        __nv_bfloat16* w3_ll  = w3_l  + (size_t)l*CC*HF;

        // ---- attention block ----
        k_rms_split<<<MM, 256>>>(h, g1 + l*CC, ah, al);
        k_mma<0><<<dim3(C3/128, MM/128), 256, MMA_SMEM>>>(
            ah, al, wq_hl, wq_ll, wkv_hl, wkv_ll, CC, nullptr, qkv, C3, CC);
        k_rope_split<<<(MM*NHH*32)/256, 256>>>(qkv, qh2, ql2, kh2, kl2, vh2, vl2);
        k_attn_mma<<<dim3(TT/64, BB*NHH), 128, ATT_SMEM2>>>(
            qh2, ql2, kh2, kl2, vh2, vl2, ah, al);
        k_mma<1><<<dim3(CC/128, MM/128), 256, MMA_SMEM>>>(
            ah, al, wo_hl, wo_ll, nullptr, nullptr, 0, h, h, CC, CC);

        // ---- MLP block ----
        k_rms_split<<<MM, 256>>>(h, g2 + l*CC, ah, al);
        k_mma<0><<<dim3(HF2/128, MM/128), 256, MMA_SMEM>>>(
            ah, al, w1_hl, w1_ll, w2_hl, w2_ll, HF, nullptr, f12, HF2, CC);
        k_silu_split<<<(MM*HF/4+255)/256, 256>>>(f12, ah, al);
        k_mma<1><<<dim3(CC/128, MM/128), 256, MMA_SMEM>>>(
            ah, al, w3_hl, w3_ll, nullptr, nullptr, 0, h, h, CC, HF);
    }

    k_rms<<<MM, 256>>>(h, gf, out);
}